// round 12
// baseline (speedup 1.0000x reference)
#include <cuda_runtime.h>
#include <math.h>

#define N_NODES 50000
#define N_EDGES 800000
#define IN_F 128
#define OUT_F 128
#define HEADS 8
#define HEAD_DIM 16
#define EDGE_F 64

typedef unsigned long long u64;

// ---------------- scratch (static device globals; no allocation) ----------------
__device__ float g_q[(size_t)N_NODES * OUT_F];
__device__ float g_k[(size_t)N_NODES * OUT_F];
__device__ float g_v[(size_t)N_NODES * OUT_F];
__device__ float g_agg[(size_t)N_NODES * OUT_F];
__device__ float g_bias[(size_t)N_EDGES * HEADS];  // CSR-ordered edge bias (+be)
__device__ int   g_deg[N_NODES];
__device__ int   g_off[N_NODES + 1];
__device__ int   g_cursor[N_NODES];
__device__ int   g_src[N_EDGES];                    // CSR-ordered source node

// ---------------- packed fp32x2 helpers (Blackwell FFMA2 path) ----------------
__device__ __forceinline__ u64 pack2(float a, float b) {
    u64 r; asm("mov.b64 %0, {%1, %2};" : "=l"(r) : "f"(a), "f"(b)); return r;
}
__device__ __forceinline__ float2 unpack2(u64 v) {
    float2 r; asm("mov.b64 {%0, %1}, %2;" : "=f"(r.x), "=f"(r.y) : "l"(v)); return r;
}
__device__ __forceinline__ void ffma2(u64& d, u64 a, u64 b) {
    asm("fma.rn.f32x2 %0, %1, %2, %0;" : "+l"(d) : "l"(a), "l"(b));
}

// ---------------- degree count ----------------
__global__ void k_count(const int* __restrict__ ei)
{
    int e = blockIdx.x * blockDim.x + threadIdx.x;
    if (e < N_EDGES) atomicAdd(&g_deg[ei[N_EDGES + e]], 1);
}

// ---------------- single-block tiled scan with next-tile prefetch ----------------
__global__ void __launch_bounds__(1024) k_scan()
{
    __shared__ int wsum[32];
    __shared__ int carry_s;
    const int tid = threadIdx.x, lane = tid & 31, w = tid >> 5;
    if (tid == 0) carry_s = 0;

    int val = (tid < N_NODES) ? g_deg[tid] : 0;
    __syncthreads();

    for (int base = 0; base < N_NODES; base += 1024) {
        int c = carry_s;
        int i = base + tid;
        int inext = i + 1024;
        int vnext = (inext < N_NODES) ? g_deg[inext] : 0;

        int incl = val;
#pragma unroll
        for (int d = 1; d < 32; d <<= 1) {
            int t = __shfl_up_sync(0xffffffffu, incl, d);
            if (lane >= d) incl += t;
        }
        if (lane == 31) wsum[w] = incl;
        __syncthreads();
        if (w == 0) {
            int s = wsum[lane];
#pragma unroll
            for (int d = 1; d < 32; d <<= 1) {
                int t = __shfl_up_sync(0xffffffffu, s, d);
                if (lane >= d) s += t;
            }
            wsum[lane] = s;
        }
        __syncthreads();
        int woff = (w == 0) ? 0 : wsum[w - 1];
        int excl = c + woff + incl - val;
        if (i < N_NODES) {
            g_off[i]    = excl;
            g_cursor[i] = excl;
        }
        __syncthreads();
        if (tid == 0) carry_s = c + wsum[31];
        val = vnext;
        __syncthreads();
    }
    if (tid == 0) g_off[N_NODES] = carry_s;
}

// ---------------- fused CSR fill + edge-bias GEMV (two-phase, low smem) --------
#define FB_EDGES 128
__global__ void __launch_bounds__(128, 8) k_fillbias(
    const int* __restrict__ ei, const float* __restrict__ ef,
    const float* __restrict__ We, const float* __restrict__ be)
{
    __shared__ float efs[FB_EDGES * 33];   // 16.9 KB (one 32-feature phase)
    __shared__ float wet[64 * 8];          // [f][h], 2 KB
    const int tid = threadIdx.x;
    const int e0 = blockIdx.x * FB_EDGES;

    for (int i = tid; i < 512; i += 128) wet[i] = We[i];

    int e = e0 + tid;
    int s = ei[e];
    int t = ei[N_EDGES + e];
    int pos = atomicAdd(&g_cursor[t], 1);
    g_src[pos] = s;

    u64 acc2[4];
    acc2[0] = pack2(be[0], be[1]);
    acc2[1] = pack2(be[2], be[3]);
    acc2[2] = pack2(be[4], be[5]);
    acc2[3] = pack2(be[6], be[7]);

#pragma unroll
    for (int ph = 0; ph < 2; ph++) {
        __syncthreads();
        for (int i = tid; i < FB_EDGES * 8; i += 128) {
            int ee = i >> 3, f4 = i & 7;
            float4 v = __ldcs(&reinterpret_cast<const float4*>(ef)
                              [(size_t)(e0 + ee) * 16 + ph * 8 + f4]);
            float* dst = &efs[ee * 33 + f4 * 4];
            dst[0] = v.x; dst[1] = v.y; dst[2] = v.z; dst[3] = v.w;
        }
        __syncthreads();

        const float* er = &efs[tid * 33];
        const float* wph = &wet[ph * 32 * 8];
#pragma unroll
        for (int f = 0; f < 32; f++) {
            float ev = er[f];
            u64 evv = pack2(ev, ev);
            const u64* w2 = reinterpret_cast<const u64*>(&wph[f * 8]);
            ffma2(acc2[0], evv, w2[0]);
            ffma2(acc2[1], evv, w2[1]);
            ffma2(acc2[2], evv, w2[2]);
            ffma2(acc2[3], evv, w2[3]);
        }
    }

    float2 r0 = unpack2(acc2[0]), r1 = unpack2(acc2[1]);
    float2 r2 = unpack2(acc2[2]), r3 = unpack2(acc2[3]);
    float4* dst = reinterpret_cast<float4*>(&g_bias[(size_t)pos * 8]);
    dst[0] = make_float4(r0.x, r0.y, r1.x, r1.y);
    dst[1] = make_float4(r2.x, r2.y, r3.x, r3.y);
}

// ---------------- QKV projection: column-paired FFMA2, x duplicated in smem ----
// Thread owns 8 adjacent output cols x 4 nodes. W pairs come straight from
// LDG.128 (no pack); x is pre-duplicated (x,x) in smem -> LDS.64 broadcast.
// Inner iter: 2 LDG.128 + 4 LDS.64 + 16 FFMA2 (pack-free critical path).
__global__ void __launch_bounds__(384) k_qkv(
    const float* __restrict__ x,
    const float* __restrict__ Wq, const float* __restrict__ bq,
    const float* __restrict__ Wk, const float* __restrict__ bk,
    const float* __restrict__ Wv, const float* __restrict__ bv)
{
    __shared__ u64 xs2[128 * 32];   // xs2[i*32+n] = (x[n][i], x[n][i]), 32 KB
    const int n0 = blockIdx.x * 32;
    const int nvalid = min(32, N_NODES - n0);
    const int tid = threadIdx.x;

    for (int j = tid; j < 1024; j += 384) {
        int n = j & 31;
        int i4 = j >> 5;
        float4 val = make_float4(0.f, 0.f, 0.f, 0.f);
        if (n < nvalid)
            val = reinterpret_cast<const float4*>(x)[(size_t)(n0 + n) * 32 + i4];
        xs2[(i4 * 4 + 0) * 32 + n] = pack2(val.x, val.x);
        xs2[(i4 * 4 + 1) * 32 + n] = pack2(val.y, val.y);
        xs2[(i4 * 4 + 2) * 32 + n] = pack2(val.z, val.z);
        xs2[(i4 * 4 + 3) * 32 + n] = pack2(val.w, val.w);
    }
    __syncthreads();

    const int m  = tid >> 7;            // 0=Q, 1=K, 2=V (warp-uniform)
    const int tt = tid & 127;
    const int co = tt & 15;             // column octet: cols 8co..8co+7
    const int ng = tt >> 4;             // node group: nodes 4ng..4ng+3 (warp-uniform)

    const float* W    = (m == 0) ? Wq : (m == 1) ? Wk : Wv;
    const float* bias = (m == 0) ? bq : (m == 1) ? bk : bv;
    float* outp       = (m == 0) ? g_q : (m == 1) ? g_k : g_v;

    u64 acc[4][4];   // [node][col-pair]
#pragma unroll
    for (int nn = 0; nn < 4; nn++)
#pragma unroll
        for (int cp = 0; cp < 4; cp++) acc[nn][cp] = 0ull;

    const u64* Wp = reinterpret_cast<const u64*>(W) + co * 4;   // row stride 64 u64

#pragma unroll 4
    for (int i = 0; i < 128; i++) {
        // W pairs: 2x LDG.128 = 4 u64, no packing needed
        u64 ww0 = Wp[i * 64 + 0];
        u64 ww1 = Wp[i * 64 + 1];
        u64 ww2 = Wp[i * 64 + 2];
        u64 ww3 = Wp[i * 64 + 3];
        const u64* xr = &xs2[i * 32 + ng * 4];
#pragma unroll
        for (int nn = 0; nn < 4; nn++) {
            u64 xx = xr[nn];            // LDS.64 broadcast (warp-uniform addr)
            ffma2(acc[nn][0], xx, ww0);
            ffma2(acc[nn][1], xx, ww1);
            ffma2(acc[nn][2], xx, ww2);
            ffma2(acc[nn][3], xx, ww3);
        }
    }

    const float4* b8 = reinterpret_cast<const float4*>(bias) + co * 2;
    float4 bA = b8[0], bB = b8[1];
#pragma unroll
    for (int nn = 0; nn < 4; nn++) {
        int node = n0 + ng * 4 + nn;
        if (node < N_NODES) {
            float2 p0 = unpack2(acc[nn][0]);
            float2 p1 = unpack2(acc[nn][1]);
            float2 p2 = unpack2(acc[nn][2]);
            float2 p3 = unpack2(acc[nn][3]);
            float4* orow = reinterpret_cast<float4*>(outp) + (size_t)node * 32 + co * 2;
            orow[0] = make_float4(p0.x + bA.x, p0.y + bA.y, p1.x + bA.z, p1.y + bA.w);
            orow[1] = make_float4(p2.x + bB.x, p2.y + bB.y, p3.x + bB.z, p3.y + bB.w);
        }
    }
}

// ---------------- fused: scores + max-free segment softmax + weighted V agg ----
__global__ void __launch_bounds__(128) k_attn()
{
    int node = (blockIdx.x * 128 + threadIdx.x) >> 5;
    if (node >= N_NODES) return;
    const int lane = threadIdx.x & 31;
    const int h = lane >> 2;

    const int start = g_off[node], end = g_off[node + 1];
    const float4 q4 = reinterpret_cast<const float4*>(g_q)[(size_t)node * 32 + lane];

    float den0 = 0.f, den1 = 0.f;
    float4 acc0 = make_float4(0.f, 0.f, 0.f, 0.f);
    float4 acc1 = make_float4(0.f, 0.f, 0.f, 0.f);

    int idx = start;
    for (; idx + 2 <= end; idx += 2) {
        int sA = g_src[idx];
        int sB = g_src[idx + 1];
        float bA = g_bias[(size_t)idx * 8 + h];
        float bB = g_bias[(size_t)(idx + 1) * 8 + h];

        float4 kA = reinterpret_cast<const float4*>(g_k)[(size_t)sA * 32 + lane];
        float4 kB = reinterpret_cast<const float4*>(g_k)[(size_t)sB * 32 + lane];
        float4 vA = reinterpret_cast<const float4*>(g_v)[(size_t)sA * 32 + lane];
        float4 vB = reinterpret_cast<const float4*>(g_v)[(size_t)sB * 32 + lane];

        float dA = (q4.x * kA.x + q4.y * kA.y + q4.z * kA.z + q4.w * kA.w) * 0.25f;
        float dB = (q4.x * kB.x + q4.y * kB.y + q4.z * kB.z + q4.w * kB.w) * 0.25f;
        dA += __shfl_xor_sync(0xffffffffu, dA, 1);
        dB += __shfl_xor_sync(0xffffffffu, dB, 1);
        dA += __shfl_xor_sync(0xffffffffu, dA, 2);
        dB += __shfl_xor_sync(0xffffffffu, dB, 2);

        float eA = __expf(dA + bA);
        float eB = __expf(dB + bB);

        den0 += eA;                 den1 += eB;
        acc0.x += eA * vA.x;        acc1.x += eB * vB.x;
        acc0.y += eA * vA.y;        acc1.y += eB * vB.y;
        acc0.z += eA * vA.z;        acc1.z += eB * vB.z;
        acc0.w += eA * vA.w;        acc1.w += eB * vB.w;
    }
    if (idx < end) {
        int s = g_src[idx];
        float b = g_bias[(size_t)idx * 8 + h];
        float4 k4 = reinterpret_cast<const float4*>(g_k)[(size_t)s * 32 + lane];
        float4 v4 = reinterpret_cast<const float4*>(g_v)[(size_t)s * 32 + lane];
        float d = (q4.x * k4.x + q4.y * k4.y + q4.z * k4.z + q4.w * k4.w) * 0.25f;
        d += __shfl_xor_sync(0xffffffffu, d, 1);
        d += __shfl_xor_sync(0xffffffffu, d, 2);
        float e = __expf(d + b);
        den0 += e;
        acc0.x += e * v4.x; acc0.y += e * v4.y;
        acc0.z += e * v4.z; acc0.w += e * v4.w;
    }

    float inv = 1.f / (den0 + den1 + 1e-30f);
    float4 r = make_float4((acc0.x + acc1.x) * inv, (acc0.y + acc1.y) * inv,
                           (acc0.z + acc1.z) * inv, (acc0.w + acc1.w) * inv);
    reinterpret_cast<float4*>(g_agg)[(size_t)node * 32 + lane] = r;
}

// ---------------- output GEMM: column-paired FFMA2 (same scheme as qkv) --------
__global__ void __launch_bounds__(128) k_out(
    const float* __restrict__ Wo, const float* __restrict__ bo,
    float* __restrict__ out)
{
    __shared__ u64 xs2[128 * 32];   // 32 KB
    const int n0 = blockIdx.x * 32;
    const int nvalid = min(32, N_NODES - n0);
    const int tid = threadIdx.x;

    for (int j = tid; j < 1024; j += 128) {
        int n = j & 31;
        int i4 = j >> 5;
        float4 val = make_float4(0.f, 0.f, 0.f, 0.f);
        if (n < nvalid)
            val = reinterpret_cast<const float4*>(g_agg)[(size_t)(n0 + n) * 32 + i4];
        xs2[(i4 * 4 + 0) * 32 + n] = pack2(val.x, val.x);
        xs2[(i4 * 4 + 1) * 32 + n] = pack2(val.y, val.y);
        xs2[(i4 * 4 + 2) * 32 + n] = pack2(val.z, val.z);
        xs2[(i4 * 4 + 3) * 32 + n] = pack2(val.w, val.w);
    }
    __syncthreads();

    const int co = tid & 15;
    const int ng = tid >> 4;

    u64 acc[4][4];
#pragma unroll
    for (int nn = 0; nn < 4; nn++)
#pragma unroll
        for (int cp = 0; cp < 4; cp++) acc[nn][cp] = 0ull;

    const u64* Wp = reinterpret_cast<const u64*>(Wo) + co * 4;

#pragma unroll 4
    for (int i = 0; i < 128; i++) {
        u64 ww0 = Wp[i * 64 + 0];
        u64 ww1 = Wp[i * 64 + 1];
        u64 ww2 = Wp[i * 64 + 2];
        u64 ww3 = Wp[i * 64 + 3];
        const u64* xr = &xs2[i * 32 + ng * 4];
#pragma unroll
        for (int nn = 0; nn < 4; nn++) {
            u64 xx = xr[nn];
            ffma2(acc[nn][0], xx, ww0);
            ffma2(acc[nn][1], xx, ww1);
            ffma2(acc[nn][2], xx, ww2);
            ffma2(acc[nn][3], xx, ww3);
        }
    }

    const float4* b8 = reinterpret_cast<const float4*>(bo) + co * 2;
    float4 bA = b8[0], bB = b8[1];
#pragma unroll
    for (int nn = 0; nn < 4; nn++) {
        int node = n0 + ng * 4 + nn;
        if (node < N_NODES) {
            float2 p0 = unpack2(acc[nn][0]);
            float2 p1 = unpack2(acc[nn][1]);
            float2 p2 = unpack2(acc[nn][2]);
            float2 p3 = unpack2(acc[nn][3]);
            float4* orow = reinterpret_cast<float4*>(out) + (size_t)node * 32 + co * 2;
            orow[0] = make_float4(p0.x + bA.x, p0.y + bA.y, p1.x + bA.z, p1.y + bA.w);
            orow[1] = make_float4(p2.x + bB.x, p2.y + bB.y, p3.x + bB.z, p3.y + bB.w);
        }
    }
}

// ---------------- launch: {count->scan->fillbias} || qkv, join, attn, out ------
extern "C" void kernel_launch(void* const* d_in, const int* in_sizes, int n_in,
                              void* d_out, int out_size)
{
    const float* x  = (const float*)d_in[0];
    const int*   ei = (const int*)  d_in[1];
    const float* ef = (const float*)d_in[2];
    const float* Wq = (const float*)d_in[3];
    const float* bq = (const float*)d_in[4];
    const float* Wk = (const float*)d_in[5];
    const float* bk = (const float*)d_in[6];
    const float* Wv = (const float*)d_in[7];
    const float* bv = (const float*)d_in[8];
    const float* We = (const float*)d_in[9];
    const float* be = (const float*)d_in[10];
    const float* Wo = (const float*)d_in[11];
    const float* bo = (const float*)d_in[12];
    float* out = (float*)d_out;

    static cudaStream_t s2 = nullptr;
    static cudaEvent_t evFork = nullptr, evJoin = nullptr;
    if (s2 == nullptr) {
        cudaStreamCreateWithFlags(&s2, cudaStreamNonBlocking);
        cudaEventCreateWithFlags(&evFork, cudaEventDisableTiming);
        cudaEventCreateWithFlags(&evJoin, cudaEventDisableTiming);
    }

    void* degPtr = nullptr;
    cudaGetSymbolAddress(&degPtr, g_deg);
    cudaMemsetAsync(degPtr, 0, N_NODES * sizeof(int), 0);

    cudaEventRecord(evFork, 0);
    cudaStreamWaitEvent(s2, evFork, 0);

    k_count   <<<(N_EDGES + 255) / 256, 256>>>(ei);                      // 1
    k_scan    <<<1, 1024>>>();                                           // 2
    k_fillbias<<<N_EDGES / FB_EDGES, FB_EDGES>>>(ei, ef, We, be);        // 3
    k_qkv     <<<(N_NODES + 31) / 32, 384, 0, s2>>>(x, Wq, bq, Wk, bk, Wv, bv); // 4 (s2, profiled)

    cudaEventRecord(evJoin, s2);
    cudaStreamWaitEvent(0, evJoin, 0);

    k_attn    <<<(N_NODES * 32 + 127) / 128, 128>>>();                   // 5
    k_out     <<<(N_NODES + 31) / 32, 128>>>(Wo, bo, out);               // 6
}

// round 13
// speedup vs baseline: 1.7018x; 1.7018x over previous
#include <cuda_runtime.h>
#include <math.h>

#define N_NODES 50000
#define N_EDGES 800000
#define IN_F 128
#define OUT_F 128
#define HEADS 8
#define HEAD_DIM 16
#define EDGE_F 64

#define N_HALF 25024   // half split, multiple of 32

typedef unsigned long long u64;

// ---------------- scratch (static device globals; no allocation) ----------------
__device__ float g_q[(size_t)N_NODES * OUT_F];
__device__ float g_k[(size_t)N_NODES * OUT_F];
__device__ float g_v[(size_t)N_NODES * OUT_F];
__device__ float g_agg[(size_t)N_NODES * OUT_F];
__device__ float g_bias[(size_t)N_EDGES * HEADS];  // CSR-ordered edge bias (+be)
__device__ int   g_deg[N_NODES];
__device__ int   g_off[N_NODES + 1];
__device__ int   g_cursor[N_NODES];
__device__ int   g_src[N_EDGES];                    // CSR-ordered source node

// ---------------- packed fp32x2 helpers (Blackwell FFMA2 path) ----------------
__device__ __forceinline__ u64 pack2(float a, float b) {
    u64 r; asm("mov.b64 %0, {%1, %2};" : "=l"(r) : "f"(a), "f"(b)); return r;
}
__device__ __forceinline__ float2 unpack2(u64 v) {
    float2 r; asm("mov.b64 {%0, %1}, %2;" : "=f"(r.x), "=f"(r.y) : "l"(v)); return r;
}
__device__ __forceinline__ void ffma2(u64& d, u64 a, u64 b) {
    asm("fma.rn.f32x2 %0, %1, %2, %0;" : "+l"(d) : "l"(a), "l"(b));
}

// ---------------- degree count ----------------
__global__ void k_count(const int* __restrict__ ei)
{
    int e = blockIdx.x * blockDim.x + threadIdx.x;
    if (e < N_EDGES) atomicAdd(&g_deg[ei[N_EDGES + e]], 1);
}

// ---------------- single-block tiled scan with next-tile prefetch ----------------
__global__ void __launch_bounds__(1024) k_scan()
{
    __shared__ int wsum[32];
    __shared__ int carry_s;
    const int tid = threadIdx.x, lane = tid & 31, w = tid >> 5;
    if (tid == 0) carry_s = 0;

    int val = (tid < N_NODES) ? g_deg[tid] : 0;
    __syncthreads();

    for (int base = 0; base < N_NODES; base += 1024) {
        int c = carry_s;
        int i = base + tid;
        int inext = i + 1024;
        int vnext = (inext < N_NODES) ? g_deg[inext] : 0;

        int incl = val;
#pragma unroll
        for (int d = 1; d < 32; d <<= 1) {
            int t = __shfl_up_sync(0xffffffffu, incl, d);
            if (lane >= d) incl += t;
        }
        if (lane == 31) wsum[w] = incl;
        __syncthreads();
        if (w == 0) {
            int s = wsum[lane];
#pragma unroll
            for (int d = 1; d < 32; d <<= 1) {
                int t = __shfl_up_sync(0xffffffffu, s, d);
                if (lane >= d) s += t;
            }
            wsum[lane] = s;
        }
        __syncthreads();
        int woff = (w == 0) ? 0 : wsum[w - 1];
        int excl = c + woff + incl - val;
        if (i < N_NODES) {
            g_off[i]    = excl;
            g_cursor[i] = excl;
        }
        __syncthreads();
        if (tid == 0) carry_s = c + wsum[31];
        val = vnext;
        __syncthreads();
    }
    if (tid == 0) g_off[N_NODES] = carry_s;
}

// ---------------- fused CSR fill + edge-bias GEMV (two-phase, low smem) --------
#define FB_EDGES 128
__global__ void __launch_bounds__(128, 8) k_fillbias(
    const int* __restrict__ ei, const float* __restrict__ ef,
    const float* __restrict__ We, const float* __restrict__ be)
{
    __shared__ float efs[FB_EDGES * 33];   // 16.9 KB (one 32-feature phase)
    __shared__ float wet[64 * 8];          // [f][h], 2 KB
    const int tid = threadIdx.x;
    const int e0 = blockIdx.x * FB_EDGES;

    for (int i = tid; i < 512; i += 128) wet[i] = We[i];

    int e = e0 + tid;
    int s = ei[e];
    int t = ei[N_EDGES + e];
    int pos = atomicAdd(&g_cursor[t], 1);
    g_src[pos] = s;

    u64 acc2[4];
    acc2[0] = pack2(be[0], be[1]);
    acc2[1] = pack2(be[2], be[3]);
    acc2[2] = pack2(be[4], be[5]);
    acc2[3] = pack2(be[6], be[7]);

#pragma unroll
    for (int ph = 0; ph < 2; ph++) {
        __syncthreads();
        for (int i = tid; i < FB_EDGES * 8; i += 128) {
            int ee = i >> 3, f4 = i & 7;
            float4 v = __ldcs(&reinterpret_cast<const float4*>(ef)
                              [(size_t)(e0 + ee) * 16 + ph * 8 + f4]);
            float* dst = &efs[ee * 33 + f4 * 4];
            dst[0] = v.x; dst[1] = v.y; dst[2] = v.z; dst[3] = v.w;
        }
        __syncthreads();

        const float* er = &efs[tid * 33];
        const float* wph = &wet[ph * 32 * 8];
#pragma unroll
        for (int f = 0; f < 32; f++) {
            float ev = er[f];
            u64 evv = pack2(ev, ev);
            const u64* w2 = reinterpret_cast<const u64*>(&wph[f * 8]);
            ffma2(acc2[0], evv, w2[0]);
            ffma2(acc2[1], evv, w2[1]);
            ffma2(acc2[2], evv, w2[2]);
            ffma2(acc2[3], evv, w2[3]);
        }
    }

    float2 r0 = unpack2(acc2[0]), r1 = unpack2(acc2[1]);
    float2 r2 = unpack2(acc2[2]), r3 = unpack2(acc2[3]);
    float4* dst = reinterpret_cast<float4*>(&g_bias[(size_t)pos * 8]);
    dst[0] = make_float4(r0.x, r0.y, r1.x, r1.y);
    dst[1] = make_float4(r2.x, r2.y, r3.x, r3.y);
}

// ---------------- QKV projection: 32-node tile, 8 nodes/thread (R10 proven) ----
__global__ void __launch_bounds__(384) k_qkv(
    const float* __restrict__ x,
    const float* __restrict__ Wq, const float* __restrict__ bq,
    const float* __restrict__ Wk, const float* __restrict__ bk,
    const float* __restrict__ Wv, const float* __restrict__ bv)
{
    __shared__ float xs[128 * 32];   // 16 KB
    const int n0 = blockIdx.x * 32;
    const int nvalid = min(32, N_NODES - n0);
    const int tid = threadIdx.x;

    for (int j = tid; j < 1024; j += 384) {
        int n = j & 31;
        int i4 = j >> 5;
        float4 val = make_float4(0.f, 0.f, 0.f, 0.f);
        if (n < nvalid)
            val = reinterpret_cast<const float4*>(x)[(size_t)(n0 + n) * 32 + i4];
        xs[(i4 * 4 + 0) * 32 + n] = val.x;
        xs[(i4 * 4 + 1) * 32 + n] = val.y;
        xs[(i4 * 4 + 2) * 32 + n] = val.z;
        xs[(i4 * 4 + 3) * 32 + n] = val.w;
    }
    __syncthreads();

    const int m  = tid >> 7;
    const int tt = tid & 127;
    const int c4q = tt & 31;
    const int nb  = (tt >> 5) * 8;

    const float* W    = (m == 0) ? Wq : (m == 1) ? Wk : Wv;
    const float* bias = (m == 0) ? bq : (m == 1) ? bk : bv;
    float* outp       = (m == 0) ? g_q : (m == 1) ? g_k : g_v;

    u64 acc[4][4];
#pragma unroll
    for (int np = 0; np < 4; np++)
#pragma unroll
        for (int c = 0; c < 4; c++) acc[np][c] = 0ull;

#pragma unroll 4
    for (int i = 0; i < 128; i++) {
        float4 w4 = reinterpret_cast<const float4*>(W)[i * 32 + c4q];
        u64 ww0 = pack2(w4.x, w4.x);
        u64 ww1 = pack2(w4.y, w4.y);
        u64 ww2 = pack2(w4.z, w4.z);
        u64 ww3 = pack2(w4.w, w4.w);
        const u64* xr = reinterpret_cast<const u64*>(&xs[i * 32 + nb]);
#pragma unroll
        for (int np = 0; np < 4; np++) {
            u64 xx = xr[np];
            ffma2(acc[np][0], xx, ww0);
            ffma2(acc[np][1], xx, ww1);
            ffma2(acc[np][2], xx, ww2);
            ffma2(acc[np][3], xx, ww3);
        }
    }

    float4 b4 = reinterpret_cast<const float4*>(bias)[c4q];
#pragma unroll
    for (int np = 0; np < 4; np++) {
        float2 p0 = unpack2(acc[np][0]);
        float2 p1 = unpack2(acc[np][1]);
        float2 p2 = unpack2(acc[np][2]);
        float2 p3 = unpack2(acc[np][3]);
        int node0 = n0 + nb + 2 * np;
        if (node0 < N_NODES) {
            float4 r0 = make_float4(p0.x + b4.x, p1.x + b4.y, p2.x + b4.z, p3.x + b4.w);
            reinterpret_cast<float4*>(outp)[(size_t)node0 * 32 + c4q] = r0;
        }
        if (node0 + 1 < N_NODES) {
            float4 r1 = make_float4(p0.y + b4.x, p1.y + b4.y, p2.y + b4.z, p3.y + b4.w);
            reinterpret_cast<float4*>(outp)[(size_t)(node0 + 1) * 32 + c4q] = r1;
        }
    }
}

// ---------------- fused: scores + max-free softmax + weighted V agg (ranged) ----
__global__ void __launch_bounds__(128) k_attn(int nbase, int nlimit)
{
    int node = nbase + ((blockIdx.x * 128 + threadIdx.x) >> 5);
    if (node >= nlimit) return;
    const int lane = threadIdx.x & 31;
    const int h = lane >> 2;

    const int start = g_off[node], end = g_off[node + 1];
    const float4 q4 = reinterpret_cast<const float4*>(g_q)[(size_t)node * 32 + lane];

    float den0 = 0.f, den1 = 0.f;
    float4 acc0 = make_float4(0.f, 0.f, 0.f, 0.f);
    float4 acc1 = make_float4(0.f, 0.f, 0.f, 0.f);

    int idx = start;
    for (; idx + 2 <= end; idx += 2) {
        int sA = g_src[idx];
        int sB = g_src[idx + 1];
        float bA = g_bias[(size_t)idx * 8 + h];
        float bB = g_bias[(size_t)(idx + 1) * 8 + h];

        float4 kA = reinterpret_cast<const float4*>(g_k)[(size_t)sA * 32 + lane];
        float4 kB = reinterpret_cast<const float4*>(g_k)[(size_t)sB * 32 + lane];
        float4 vA = reinterpret_cast<const float4*>(g_v)[(size_t)sA * 32 + lane];
        float4 vB = reinterpret_cast<const float4*>(g_v)[(size_t)sB * 32 + lane];

        float dA = (q4.x * kA.x + q4.y * kA.y + q4.z * kA.z + q4.w * kA.w) * 0.25f;
        float dB = (q4.x * kB.x + q4.y * kB.y + q4.z * kB.z + q4.w * kB.w) * 0.25f;
        dA += __shfl_xor_sync(0xffffffffu, dA, 1);
        dB += __shfl_xor_sync(0xffffffffu, dB, 1);
        dA += __shfl_xor_sync(0xffffffffu, dA, 2);
        dB += __shfl_xor_sync(0xffffffffu, dB, 2);

        float eA = __expf(dA + bA);
        float eB = __expf(dB + bB);

        den0 += eA;                 den1 += eB;
        acc0.x += eA * vA.x;        acc1.x += eB * vB.x;
        acc0.y += eA * vA.y;        acc1.y += eB * vB.y;
        acc0.z += eA * vA.z;        acc1.z += eB * vB.z;
        acc0.w += eA * vA.w;        acc1.w += eB * vB.w;
    }
    if (idx < end) {
        int s = g_src[idx];
        float b = g_bias[(size_t)idx * 8 + h];
        float4 k4 = reinterpret_cast<const float4*>(g_k)[(size_t)s * 32 + lane];
        float4 v4 = reinterpret_cast<const float4*>(g_v)[(size_t)s * 32 + lane];
        float d = (q4.x * k4.x + q4.y * k4.y + q4.z * k4.z + q4.w * k4.w) * 0.25f;
        d += __shfl_xor_sync(0xffffffffu, d, 1);
        d += __shfl_xor_sync(0xffffffffu, d, 2);
        float e = __expf(d + b);
        den0 += e;
        acc0.x += e * v4.x; acc0.y += e * v4.y;
        acc0.z += e * v4.z; acc0.w += e * v4.w;
    }

    float inv = 1.f / (den0 + den1 + 1e-30f);
    float4 r = make_float4((acc0.x + acc1.x) * inv, (acc0.y + acc1.y) * inv,
                           (acc0.z + acc1.z) * inv, (acc0.w + acc1.w) * inv);
    reinterpret_cast<float4*>(g_agg)[(size_t)node * 32 + lane] = r;
}

// ---------------- output GEMM: 32-node tile, 8 nodes/thread (ranged) ----------
__global__ void __launch_bounds__(128) k_out(
    const float* __restrict__ Wo, const float* __restrict__ bo,
    float* __restrict__ out, int nbase, int nlimit)
{
    __shared__ float xs[128 * 32];
    const int n0 = nbase + blockIdx.x * 32;
    const int nvalid = min(32, nlimit - n0);
    const int tid = threadIdx.x;

    for (int j = tid; j < 1024; j += 128) {
        int n = j & 31;
        int i4 = j >> 5;
        float4 val = make_float4(0.f, 0.f, 0.f, 0.f);
        if (n < nvalid)
            val = reinterpret_cast<const float4*>(g_agg)[(size_t)(n0 + n) * 32 + i4];
        xs[(i4 * 4 + 0) * 32 + n] = val.x;
        xs[(i4 * 4 + 1) * 32 + n] = val.y;
        xs[(i4 * 4 + 2) * 32 + n] = val.z;
        xs[(i4 * 4 + 3) * 32 + n] = val.w;
    }
    __syncthreads();

    const int c4q = tid & 31;
    const int nb  = (tid >> 5) * 8;

    u64 acc[4][4];
#pragma unroll
    for (int np = 0; np < 4; np++)
#pragma unroll
        for (int c = 0; c < 4; c++) acc[np][c] = 0ull;

#pragma unroll 4
    for (int i = 0; i < 128; i++) {
        float4 w4 = reinterpret_cast<const float4*>(Wo)[i * 32 + c4q];
        u64 ww0 = pack2(w4.x, w4.x);
        u64 ww1 = pack2(w4.y, w4.y);
        u64 ww2 = pack2(w4.z, w4.z);
        u64 ww3 = pack2(w4.w, w4.w);
        const u64* xr = reinterpret_cast<const u64*>(&xs[i * 32 + nb]);
#pragma unroll
        for (int np = 0; np < 4; np++) {
            u64 xx = xr[np];
            ffma2(acc[np][0], xx, ww0);
            ffma2(acc[np][1], xx, ww1);
            ffma2(acc[np][2], xx, ww2);
            ffma2(acc[np][3], xx, ww3);
        }
    }

    float4 b4 = reinterpret_cast<const float4*>(bo)[c4q];
#pragma unroll
    for (int np = 0; np < 4; np++) {
        float2 p0 = unpack2(acc[np][0]);
        float2 p1 = unpack2(acc[np][1]);
        float2 p2 = unpack2(acc[np][2]);
        float2 p3 = unpack2(acc[np][3]);
        int node0 = n0 + nb + 2 * np;
        if (node0 < nlimit) {
            float4 r0 = make_float4(p0.x + b4.x, p1.x + b4.y, p2.x + b4.z, p3.x + b4.w);
            reinterpret_cast<float4*>(out)[(size_t)node0 * 32 + c4q] = r0;
        }
        if (node0 + 1 < nlimit) {
            float4 r1 = make_float4(p0.y + b4.x, p1.y + b4.y, p2.y + b4.z, p3.y + b4.w);
            reinterpret_cast<float4*>(out)[(size_t)(node0 + 1) * 32 + c4q] = r1;
        }
    }
}

// ---- launch: {count,scan,fillbias} || qkv ; attn_A ; (attn_B || out_A) ; out_B
extern "C" void kernel_launch(void* const* d_in, const int* in_sizes, int n_in,
                              void* d_out, int out_size)
{
    const float* x  = (const float*)d_in[0];
    const int*   ei = (const int*)  d_in[1];
    const float* ef = (const float*)d_in[2];
    const float* Wq = (const float*)d_in[3];
    const float* bq = (const float*)d_in[4];
    const float* Wk = (const float*)d_in[5];
    const float* bk = (const float*)d_in[6];
    const float* Wv = (const float*)d_in[7];
    const float* bv = (const float*)d_in[8];
    const float* We = (const float*)d_in[9];
    const float* be = (const float*)d_in[10];
    const float* Wo = (const float*)d_in[11];
    const float* bo = (const float*)d_in[12];
    float* out = (float*)d_out;

    static cudaStream_t s2 = nullptr;
    static cudaEvent_t evFork = nullptr, evJoin = nullptr;
    static cudaEvent_t evA = nullptr, evB = nullptr, evOut = nullptr;
    if (s2 == nullptr) {
        cudaStreamCreateWithFlags(&s2, cudaStreamNonBlocking);
        cudaEventCreateWithFlags(&evFork, cudaEventDisableTiming);
        cudaEventCreateWithFlags(&evJoin, cudaEventDisableTiming);
        cudaEventCreateWithFlags(&evA,    cudaEventDisableTiming);
        cudaEventCreateWithFlags(&evB,    cudaEventDisableTiming);
        cudaEventCreateWithFlags(&evOut,  cudaEventDisableTiming);
    }

    void* degPtr = nullptr;
    cudaGetSymbolAddress(&degPtr, g_deg);
    cudaMemsetAsync(degPtr, 0, N_NODES * sizeof(int), 0);

    cudaEventRecord(evFork, 0);
    cudaStreamWaitEvent(s2, evFork, 0);

    k_count   <<<(N_EDGES + 255) / 256, 256>>>(ei);                      // 1
    k_scan    <<<1, 1024>>>();                                           // 2
    k_fillbias<<<N_EDGES / FB_EDGES, FB_EDGES>>>(ei, ef, We, be);        // 3
    k_qkv     <<<(N_NODES + 31) / 32, 384, 0, s2>>>(x, Wq, bq, Wk, bk, Wv, bv); // 4 (s2)

    // join: attn needs qkv (s2) AND fillbias (stream 0)
    cudaEventRecord(evJoin, s2);
    cudaStreamWaitEvent(0, evJoin, 0);

    // attn half A, then B; out half A overlaps attn half B on s2
    k_attn<<<(N_HALF * 32 + 127) / 128, 128>>>(0, N_HALF);               // 5
    cudaEventRecord(evA, 0);
    k_attn<<<((N_NODES - N_HALF) * 32 + 127) / 128, 128>>>(N_HALF, N_NODES); // 6
    cudaEventRecord(evB, 0);

    cudaStreamWaitEvent(s2, evA, 0);
    k_out<<<N_HALF / 32, 128, 0, s2>>>(Wo, bo, out, 0, N_HALF);          // 7 (s2)
    cudaStreamWaitEvent(s2, evB, 0);
    k_out<<<(N_NODES - N_HALF + 31) / 32, 128, 0, s2>>>(Wo, bo, out, N_HALF, N_NODES); // 8 (s2)

    // join s2 back into the capture origin stream
    cudaEventRecord(evOut, s2);
    cudaStreamWaitEvent(0, evOut, 0);
}

// round 14
// speedup vs baseline: 1.8798x; 1.1046x over previous
#include <cuda_runtime.h>
#include <math.h>

#define N_NODES 50000
#define N_EDGES 800000
#define IN_F 128
#define OUT_F 128
#define HEADS 8
#define HEAD_DIM 16
#define EDGE_F 64

#define KI 16           // K-chunk rows staged per buffer
#define NCHUNK 8        // 128 / KI

typedef unsigned long long u64;

// ---------------- scratch (static device globals; no allocation) ----------------
__device__ float g_q[(size_t)N_NODES * OUT_F];
__device__ float g_k[(size_t)N_NODES * OUT_F];
__device__ float g_v[(size_t)N_NODES * OUT_F];
__device__ float g_agg[(size_t)N_NODES * OUT_F];
__device__ float g_bias[(size_t)N_EDGES * HEADS];  // CSR-ordered edge bias (+be)
__device__ int   g_deg[N_NODES];
__device__ int   g_off[N_NODES + 1];
__device__ int   g_cursor[N_NODES];
__device__ int   g_src[N_EDGES];                    // CSR-ordered source node

// ---------------- packed fp32x2 helpers (Blackwell FFMA2 path) ----------------
__device__ __forceinline__ u64 pack2(float a, float b) {
    u64 r; asm("mov.b64 %0, {%1, %2};" : "=l"(r) : "f"(a), "f"(b)); return r;
}
__device__ __forceinline__ float2 unpack2(u64 v) {
    float2 r; asm("mov.b64 {%0, %1}, %2;" : "=f"(r.x), "=f"(r.y) : "l"(v)); return r;
}
__device__ __forceinline__ void ffma2(u64& d, u64 a, u64 b) {
    asm("fma.rn.f32x2 %0, %1, %2, %0;" : "+l"(d) : "l"(a), "l"(b));
}

// ---------------- degree count ----------------
__global__ void k_count(const int* __restrict__ ei)
{
    int e = blockIdx.x * blockDim.x + threadIdx.x;
    if (e < N_EDGES) atomicAdd(&g_deg[ei[N_EDGES + e]], 1);
}

// ---------------- single-block tiled scan with next-tile prefetch ----------------
__global__ void __launch_bounds__(1024) k_scan()
{
    __shared__ int wsum[32];
    __shared__ int carry_s;
    const int tid = threadIdx.x, lane = tid & 31, w = tid >> 5;
    if (tid == 0) carry_s = 0;

    int val = (tid < N_NODES) ? g_deg[tid] : 0;
    __syncthreads();

    for (int base = 0; base < N_NODES; base += 1024) {
        int c = carry_s;
        int i = base + tid;
        int inext = i + 1024;
        int vnext = (inext < N_NODES) ? g_deg[inext] : 0;

        int incl = val;
#pragma unroll
        for (int d = 1; d < 32; d <<= 1) {
            int t = __shfl_up_sync(0xffffffffu, incl, d);
            if (lane >= d) incl += t;
        }
        if (lane == 31) wsum[w] = incl;
        __syncthreads();
        if (w == 0) {
            int s = wsum[lane];
#pragma unroll
            for (int d = 1; d < 32; d <<= 1) {
                int t = __shfl_up_sync(0xffffffffu, s, d);
                if (lane >= d) s += t;
            }
            wsum[lane] = s;
        }
        __syncthreads();
        int woff = (w == 0) ? 0 : wsum[w - 1];
        int excl = c + woff + incl - val;
        if (i < N_NODES) {
            g_off[i]    = excl;
            g_cursor[i] = excl;
        }
        __syncthreads();
        if (tid == 0) carry_s = c + wsum[31];
        val = vnext;
        __syncthreads();
    }
    if (tid == 0) g_off[N_NODES] = carry_s;
}

// ---------------- fused CSR fill + edge-bias GEMV (two-phase, low smem) --------
#define FB_EDGES 128
__global__ void __launch_bounds__(128, 8) k_fillbias(
    const int* __restrict__ ei, const float* __restrict__ ef,
    const float* __restrict__ We, const float* __restrict__ be)
{
    __shared__ float efs[FB_EDGES * 33];   // 16.9 KB (one 32-feature phase)
    __shared__ float wet[64 * 8];          // [f][h], 2 KB
    const int tid = threadIdx.x;
    const int e0 = blockIdx.x * FB_EDGES;

    for (int i = tid; i < 512; i += 128) wet[i] = We[i];

    int e = e0 + tid;
    int s = ei[e];
    int t = ei[N_EDGES + e];
    int pos = atomicAdd(&g_cursor[t], 1);
    g_src[pos] = s;

    u64 acc2[4];
    acc2[0] = pack2(be[0], be[1]);
    acc2[1] = pack2(be[2], be[3]);
    acc2[2] = pack2(be[4], be[5]);
    acc2[3] = pack2(be[6], be[7]);

#pragma unroll
    for (int ph = 0; ph < 2; ph++) {
        __syncthreads();
        for (int i = tid; i < FB_EDGES * 8; i += 128) {
            int ee = i >> 3, f4 = i & 7;
            float4 v = __ldcs(&reinterpret_cast<const float4*>(ef)
                              [(size_t)(e0 + ee) * 16 + ph * 8 + f4]);
            float* dst = &efs[ee * 33 + f4 * 4];
            dst[0] = v.x; dst[1] = v.y; dst[2] = v.z; dst[3] = v.w;
        }
        __syncthreads();

        const float* er = &efs[tid * 33];
        const float* wph = &wet[ph * 32 * 8];
#pragma unroll
        for (int f = 0; f < 32; f++) {
            float ev = er[f];
            u64 evv = pack2(ev, ev);
            const u64* w2 = reinterpret_cast<const u64*>(&wph[f * 8]);
            ffma2(acc2[0], evv, w2[0]);
            ffma2(acc2[1], evv, w2[1]);
            ffma2(acc2[2], evv, w2[2]);
            ffma2(acc2[3], evv, w2[3]);
        }
    }

    float2 r0 = unpack2(acc2[0]), r1 = unpack2(acc2[1]);
    float2 r2 = unpack2(acc2[2]), r3 = unpack2(acc2[3]);
    float4* dst = reinterpret_cast<float4*>(&g_bias[(size_t)pos * 8]);
    dst[0] = make_float4(r0.x, r0.y, r1.x, r1.y);
    dst[1] = make_float4(r2.x, r2.y, r3.x, r3.y);
}

// ---------------- QKV projection: W double-buffered in smem ----------------
// Dynamic smem: xs (4096 f) + per-matrix W chunks (3 * 2 buf * 2048 f) = 64 KB.
// Inner loop reads W via conflict-free LDS.128 (29 cyc, covered) instead of
// a ~230-cyc L2 LDG -> fma pipe can saturate at 2 blocks/SM.
__global__ void __launch_bounds__(384) k_qkv(
    const float* __restrict__ x,
    const float* __restrict__ Wq, const float* __restrict__ bq,
    const float* __restrict__ Wk, const float* __restrict__ bk,
    const float* __restrict__ Wv, const float* __restrict__ bv)
{
    extern __shared__ float sm[];
    float* xs = sm;                       // xs[i*32 + n], 16 KB
    const int n0 = blockIdx.x * 32;
    const int nvalid = min(32, N_NODES - n0);
    const int tid = threadIdx.x;

    for (int j = tid; j < 1024; j += 384) {
        int n = j & 31;
        int i4 = j >> 5;
        float4 val = make_float4(0.f, 0.f, 0.f, 0.f);
        if (n < nvalid)
            val = reinterpret_cast<const float4*>(x)[(size_t)(n0 + n) * 32 + i4];
        xs[(i4 * 4 + 0) * 32 + n] = val.x;
        xs[(i4 * 4 + 1) * 32 + n] = val.y;
        xs[(i4 * 4 + 2) * 32 + n] = val.z;
        xs[(i4 * 4 + 3) * 32 + n] = val.w;
    }

    const int m  = tid >> 7;             // 0=Q, 1=K, 2=V (warp-uniform)
    const int tt = tid & 127;
    const int c4q = tt & 31;
    const int nb  = (tt >> 5) * 8;

    const float* W    = (m == 0) ? Wq : (m == 1) ? Wk : Wv;
    const float* bias = (m == 0) ? bq : (m == 1) ? bk : bv;
    float* outp       = (m == 0) ? g_q : (m == 1) ? g_k : g_v;

    float* wsm = sm + 4096 + m * 4096;   // this matrix's 2 buffers (2*2048 f)
    const float4* Wg = reinterpret_cast<const float4*>(W);

    // stage chunk 0 into buf 0 (coalesced: 512 float4 / 128 threads)
    {
        float4* wsb = reinterpret_cast<float4*>(wsm);
#pragma unroll
        for (int k2 = 0; k2 < 4; k2++) wsb[tt + 128 * k2] = Wg[tt + 128 * k2];
    }
    __syncthreads();

    u64 acc[4][4];
#pragma unroll
    for (int np = 0; np < 4; np++)
#pragma unroll
        for (int c = 0; c < 4; c++) acc[np][c] = 0ull;

#pragma unroll 1
    for (int cc = 0; cc < NCHUNK; cc++) {
        if (cc < NCHUNK - 1) {
            const float4* Wn = Wg + (cc + 1) * (KI * 32);
            float4* wsb = reinterpret_cast<float4*>(wsm + ((cc + 1) & 1) * 2048);
#pragma unroll
            for (int k2 = 0; k2 < 4; k2++) wsb[tt + 128 * k2] = Wn[tt + 128 * k2];
        }
        const float4* wsr = reinterpret_cast<const float4*>(wsm + (cc & 1) * 2048);
        const float* xsc = &xs[cc * KI * 32];
#pragma unroll
        for (int il = 0; il < KI; il++) {
            float4 w4 = wsr[il * 32 + c4q];
            u64 ww0 = pack2(w4.x, w4.x);
            u64 ww1 = pack2(w4.y, w4.y);
            u64 ww2 = pack2(w4.z, w4.z);
            u64 ww3 = pack2(w4.w, w4.w);
            const u64* xr = reinterpret_cast<const u64*>(&xsc[il * 32 + nb]);
#pragma unroll
            for (int np = 0; np < 4; np++) {
                u64 xx = xr[np];
                ffma2(acc[np][0], xx, ww0);
                ffma2(acc[np][1], xx, ww1);
                ffma2(acc[np][2], xx, ww2);
                ffma2(acc[np][3], xx, ww3);
            }
        }
        __syncthreads();
    }

    float4 b4 = reinterpret_cast<const float4*>(bias)[c4q];
#pragma unroll
    for (int np = 0; np < 4; np++) {
        float2 p0 = unpack2(acc[np][0]);
        float2 p1 = unpack2(acc[np][1]);
        float2 p2 = unpack2(acc[np][2]);
        float2 p3 = unpack2(acc[np][3]);
        int node0 = n0 + nb + 2 * np;
        if (node0 < N_NODES) {
            float4 r0 = make_float4(p0.x + b4.x, p1.x + b4.y, p2.x + b4.z, p3.x + b4.w);
            reinterpret_cast<float4*>(outp)[(size_t)node0 * 32 + c4q] = r0;
        }
        if (node0 + 1 < N_NODES) {
            float4 r1 = make_float4(p0.y + b4.x, p1.y + b4.y, p2.y + b4.z, p3.y + b4.w);
            reinterpret_cast<float4*>(outp)[(size_t)(node0 + 1) * 32 + c4q] = r1;
        }
    }
}

// ---------------- fused: scores + max-free segment softmax + weighted V agg ----
__global__ void __launch_bounds__(128) k_attn()
{
    int node = (blockIdx.x * 128 + threadIdx.x) >> 5;
    if (node >= N_NODES) return;
    const int lane = threadIdx.x & 31;
    const int h = lane >> 2;

    const int start = g_off[node], end = g_off[node + 1];
    const float4 q4 = reinterpret_cast<const float4*>(g_q)[(size_t)node * 32 + lane];

    float den0 = 0.f, den1 = 0.f;
    float4 acc0 = make_float4(0.f, 0.f, 0.f, 0.f);
    float4 acc1 = make_float4(0.f, 0.f, 0.f, 0.f);

    int idx = start;
    for (; idx + 2 <= end; idx += 2) {
        int sA = g_src[idx];
        int sB = g_src[idx + 1];
        float bA = g_bias[(size_t)idx * 8 + h];
        float bB = g_bias[(size_t)(idx + 1) * 8 + h];

        float4 kA = reinterpret_cast<const float4*>(g_k)[(size_t)sA * 32 + lane];
        float4 kB = reinterpret_cast<const float4*>(g_k)[(size_t)sB * 32 + lane];
        float4 vA = reinterpret_cast<const float4*>(g_v)[(size_t)sA * 32 + lane];
        float4 vB = reinterpret_cast<const float4*>(g_v)[(size_t)sB * 32 + lane];

        float dA = (q4.x * kA.x + q4.y * kA.y + q4.z * kA.z + q4.w * kA.w) * 0.25f;
        float dB = (q4.x * kB.x + q4.y * kB.y + q4.z * kB.z + q4.w * kB.w) * 0.25f;
        dA += __shfl_xor_sync(0xffffffffu, dA, 1);
        dB += __shfl_xor_sync(0xffffffffu, dB, 1);
        dA += __shfl_xor_sync(0xffffffffu, dA, 2);
        dB += __shfl_xor_sync(0xffffffffu, dB, 2);

        float eA = __expf(dA + bA);
        float eB = __expf(dB + bB);

        den0 += eA;                 den1 += eB;
        acc0.x += eA * vA.x;        acc1.x += eB * vB.x;
        acc0.y += eA * vA.y;        acc1.y += eB * vB.y;
        acc0.z += eA * vA.z;        acc1.z += eB * vB.z;
        acc0.w += eA * vA.w;        acc1.w += eB * vB.w;
    }
    if (idx < end) {
        int s = g_src[idx];
        float b = g_bias[(size_t)idx * 8 + h];
        float4 k4 = reinterpret_cast<const float4*>(g_k)[(size_t)s * 32 + lane];
        float4 v4 = reinterpret_cast<const float4*>(g_v)[(size_t)s * 32 + lane];
        float d = (q4.x * k4.x + q4.y * k4.y + q4.z * k4.z + q4.w * k4.w) * 0.25f;
        d += __shfl_xor_sync(0xffffffffu, d, 1);
        d += __shfl_xor_sync(0xffffffffu, d, 2);
        float e = __expf(d + b);
        den0 += e;
        acc0.x += e * v4.x; acc0.y += e * v4.y;
        acc0.z += e * v4.z; acc0.w += e * v4.w;
    }

    float inv = 1.f / (den0 + den1 + 1e-30f);
    float4 r = make_float4((acc0.x + acc1.x) * inv, (acc0.y + acc1.y) * inv,
                           (acc0.z + acc1.z) * inv, (acc0.w + acc1.w) * inv);
    reinterpret_cast<float4*>(g_agg)[(size_t)node * 32 + lane] = r;
}

// ---------------- output GEMM: W double-buffered in smem (static 32 KB) --------
__global__ void __launch_bounds__(128) k_out(
    const float* __restrict__ Wo, const float* __restrict__ bo,
    float* __restrict__ out)
{
    __shared__ float xs[128 * 32];     // 16 KB
    __shared__ float ws[2 * KI * 128]; // 16 KB (2 buffers)
    const int n0 = blockIdx.x * 32;
    const int nvalid = min(32, N_NODES - n0);
    const int tid = threadIdx.x;

    for (int j = tid; j < 1024; j += 128) {
        int n = j & 31;
        int i4 = j >> 5;
        float4 val = make_float4(0.f, 0.f, 0.f, 0.f);
        if (n < nvalid)
            val = reinterpret_cast<const float4*>(g_agg)[(size_t)(n0 + n) * 32 + i4];
        xs[(i4 * 4 + 0) * 32 + n] = val.x;
        xs[(i4 * 4 + 1) * 32 + n] = val.y;
        xs[(i4 * 4 + 2) * 32 + n] = val.z;
        xs[(i4 * 4 + 3) * 32 + n] = val.w;
    }

    const int c4q = tid & 31;
    const int nb  = (tid >> 5) * 8;
    const float4* Wg = reinterpret_cast<const float4*>(Wo);

    {
        float4* wsb = reinterpret_cast<float4*>(ws);
#pragma unroll
        for (int k2 = 0; k2 < 4; k2++) wsb[tid + 128 * k2] = Wg[tid + 128 * k2];
    }
    __syncthreads();

    u64 acc[4][4];
#pragma unroll
    for (int np = 0; np < 4; np++)
#pragma unroll
        for (int c = 0; c < 4; c++) acc[np][c] = 0ull;

#pragma unroll 1
    for (int cc = 0; cc < NCHUNK; cc++) {
        if (cc < NCHUNK - 1) {
            const float4* Wn = Wg + (cc + 1) * (KI * 32);
            float4* wsb = reinterpret_cast<float4*>(ws + ((cc + 1) & 1) * 2048);
#pragma unroll
            for (int k2 = 0; k2 < 4; k2++) wsb[tid + 128 * k2] = Wn[tid + 128 * k2];
        }
        const float4* wsr = reinterpret_cast<const float4*>(ws + (cc & 1) * 2048);
        const float* xsc = &xs[cc * KI * 32];
#pragma unroll
        for (int il = 0; il < KI; il++) {
            float4 w4 = wsr[il * 32 + c4q];
            u64 ww0 = pack2(w4.x, w4.x);
            u64 ww1 = pack2(w4.y, w4.y);
            u64 ww2 = pack2(w4.z, w4.z);
            u64 ww3 = pack2(w4.w, w4.w);
            const u64* xr = reinterpret_cast<const u64*>(&xsc[il * 32 + nb]);
#pragma unroll
            for (int np = 0; np < 4; np++) {
                u64 xx = xr[np];
                ffma2(acc[np][0], xx, ww0);
                ffma2(acc[np][1], xx, ww1);
                ffma2(acc[np][2], xx, ww2);
                ffma2(acc[np][3], xx, ww3);
            }
        }
        __syncthreads();
    }

    float4 b4 = reinterpret_cast<const float4*>(bo)[c4q];
#pragma unroll
    for (int np = 0; np < 4; np++) {
        float2 p0 = unpack2(acc[np][0]);
        float2 p1 = unpack2(acc[np][1]);
        float2 p2 = unpack2(acc[np][2]);
        float2 p3 = unpack2(acc[np][3]);
        int node0 = n0 + nb + 2 * np;
        if (node0 < N_NODES) {
            float4 r0 = make_float4(p0.x + b4.x, p1.x + b4.y, p2.x + b4.z, p3.x + b4.w);
            reinterpret_cast<float4*>(out)[(size_t)node0 * 32 + c4q] = r0;
        }
        if (node0 + 1 < N_NODES) {
            float4 r1 = make_float4(p0.y + b4.x, p1.y + b4.y, p2.y + b4.z, p3.y + b4.w);
            reinterpret_cast<float4*>(out)[(size_t)(node0 + 1) * 32 + c4q] = r1;
        }
    }
}

// ---------------- launch: {count->scan->fillbias} || qkv, join, attn, out ------
#define QKV_SMEM (16384 * 4)   // 64 KB dynamic

extern "C" void kernel_launch(void* const* d_in, const int* in_sizes, int n_in,
                              void* d_out, int out_size)
{
    const float* x  = (const float*)d_in[0];
    const int*   ei = (const int*)  d_in[1];
    const float* ef = (const float*)d_in[2];
    const float* Wq = (const float*)d_in[3];
    const float* bq = (const float*)d_in[4];
    const float* Wk = (const float*)d_in[5];
    const float* bk = (const float*)d_in[6];
    const float* Wv = (const float*)d_in[7];
    const float* bv = (const float*)d_in[8];
    const float* We = (const float*)d_in[9];
    const float* be = (const float*)d_in[10];
    const float* Wo = (const float*)d_in[11];
    const float* bo = (const float*)d_in[12];
    float* out = (float*)d_out;

    static cudaStream_t s2 = nullptr;
    static cudaEvent_t evFork = nullptr, evJoin = nullptr;
    if (s2 == nullptr) {
        cudaStreamCreateWithFlags(&s2, cudaStreamNonBlocking);
        cudaEventCreateWithFlags(&evFork, cudaEventDisableTiming);
        cudaEventCreateWithFlags(&evJoin, cudaEventDisableTiming);
        cudaFuncSetAttribute(k_qkv, cudaFuncAttributeMaxDynamicSharedMemorySize,
                             QKV_SMEM);
    }

    void* degPtr = nullptr;
    cudaGetSymbolAddress(&degPtr, g_deg);
    cudaMemsetAsync(degPtr, 0, N_NODES * sizeof(int), 0);

    cudaEventRecord(evFork, 0);
    cudaStreamWaitEvent(s2, evFork, 0);

    k_count   <<<(N_EDGES + 255) / 256, 256>>>(ei);                      // 1
    k_scan    <<<1, 1024>>>();                                           // 2
    k_fillbias<<<N_EDGES / FB_EDGES, FB_EDGES>>>(ei, ef, We, be);        // 3
    k_qkv     <<<(N_NODES + 31) / 32, 384, QKV_SMEM, s2>>>(x, Wq, bq, Wk, bk, Wv, bv); // 4 (s2, profiled)

    cudaEventRecord(evJoin, s2);
    cudaStreamWaitEvent(0, evJoin, 0);

    k_attn    <<<(N_NODES * 32 + 127) / 128, 128>>>();                   // 5
    k_out     <<<(N_NODES + 31) / 32, 128>>>(Wo, bo, out);               // 6
}